// round 16
// baseline (speedup 1.0000x reference)
#include <cuda_runtime.h>
#include <cstdint>
#include <cmath>

// FIRE bias: out[1,H,S,S], H=12, S=2048, W=32. Two kernels:
//   fire_pre  — ONE WARP, barrier-free (shfl-based): builds 33x12 {slope,icept}
//               table + sorted thresholds from the 440-float weights.
//   fire_main — one block per row i (2048x512): piecewise-linear evaluation,
//               region via binary search + monotone walk; write-roofline bound.
// R14 lesson: per-block redundant table build (fusion) stalls the store stream
// at block barriers -> 57us. Shared precompute + PDL is the right shape.

#define SDIM 2048
#define HDIM 12
#define WDIM 32
#define NREG 33
#define FULLMASK 0xFFFFFFFFu

__device__ float  g_c, g_thr;
__device__ float  g_sortedT[WDIM];
__device__ float2 g_tab[NREG * HDIM];   // {slope, intercept} (unscaled)

__global__ void fire_pre(const float* __restrict__ w1,
                         const float* __restrict__ b1,
                         const float* __restrict__ w2,
                         const float* __restrict__ b2,
                         const float* __restrict__ cp,
                         const float* __restrict__ Lm,
                         const float* __restrict__ iL) {
    const int lane = threadIdx.x;   // single warp: 0..31

    const float w1v = w1[lane];
    const float b1v = b1[lane];
    if (lane == 0) { g_c = *cp; g_thr = fabsf((*Lm) * (*iL)); }

    // threshold per lane
    const float t = (w1v != 0.0f) ? (-b1v / w1v) : 0.0f;

    // rank via shfl scan (stable by lane index)
    int rank = 0;
#pragma unroll
    for (int k = 0; k < WDIM; k++) {
        const float tk = __shfl_sync(FULLMASK, t, k);
        rank += (tk < t || (tk == t && k < lane)) ? 1 : 0;
    }
    g_sortedT[rank] = t;

    // inverse permutation not needed: for table entry (r,h) we iterate w and use
    // each w's rank directly (broadcast w1/b1/rank via shfl).
#pragma unroll
    for (int e = lane; e < NREG * HDIM; e += WDIM) {
        const int r = e / HDIM;
        const int h = e % HDIM;
        float sl = 0.0f, ic = 0.0f;
#pragma unroll
        for (int w = 0; w < WDIM; w++) {
            const float w1w = __shfl_sync(FULLMASK, w1v, w);
            const float b1w = __shfl_sync(FULLMASK, b1v, w);
            const int   rkw = __shfl_sync(FULLMASK, rank, w);
            bool act;
            if (w1w > 0.0f)      act = (rkw < r);
            else if (w1w < 0.0f) act = (rkw >= r);
            else                 act = (b1w > 0.0f);
            if (act) {
                const float w2v = w2[h * WDIM + w];
                sl += w1w * w2v;
                ic += b1w * w2v;
            }
        }
        g_tab[e] = make_float2(sl, ic + b2[h]);
    }
#if __CUDA_ARCH__ >= 900
    cudaTriggerProgrammaticLaunchCompletion();
#endif
}

__global__ __launch_bounds__(512, 3)
void fire_main(float* __restrict__ out) {
#if __CUDA_ARCH__ >= 900
    cudaGridDependencySynchronize();
#endif
    __shared__ float2 shTab[NREG * HDIM];   // slope pre-multiplied by invLN(i)
    __shared__ float  sLRT[64];             // t_k * LN(i), padded with +inf
    const int tid = threadIdx.x;
    const int i   = blockIdx.x;

    const float c   = g_c;
    const float thr = g_thr;
    // log-norm for this row (uniform across block; cheap MUFU math)
    const float pn    = fmaxf((float)i, thr) + 1e-6f;
    const float ln    = __logf(fabsf(c * pn) + 1.000001f);
    const float invln = __fdividef(1.0f, ln);

    for (int k = tid; k < NREG * HDIM; k += 512) {
        float2 v = g_tab[k];
        v.x *= invln;
        shTab[k] = v;
    }
    if (tid < 64)
        sLRT[tid] = (tid < WDIM) ? g_sortedT[tid] * ln : __int_as_float(0x7f800000);
    __syncthreads();

    const int j0 = tid * 4;
    const float K = fmaf(1e-6f, c, 1.000001f);   // (d+eps)*c + 1 + eps = d*c + K
    const float lr0 = __logf(fmaf((float)abs(i - j0),       c, K));
    const float lr1 = __logf(fmaf((float)abs(i - (j0 + 1)), c, K));
    const float lr2 = __logf(fmaf((float)abs(i - (j0 + 2)), c, K));
    const float lr3 = __logf(fmaf((float)abs(i - (j0 + 3)), c, K));

    // binary search for lr0's region: r = #{k : lr >= t_k*LN}
    int r0 = 0;
#pragma unroll
    for (int s = 32; s >= 1; s >>= 1)
        r0 += (lr0 >= sLRT[r0 + s - 1]) ? s : 0;
    // monotone walk for the remaining consecutive d's (expected ~0 steps)
    int r1 = r0;
    while (lr1 >= sLRT[r1]) r1++;
    while (r1 > 0 && lr1 < sLRT[r1 - 1]) r1--;
    int r2 = r1;
    while (lr2 >= sLRT[r2]) r2++;
    while (r2 > 0 && lr2 < sLRT[r2 - 1]) r2--;
    int r3 = r2;
    while (lr3 >= sLRT[r3]) r3++;
    while (r3 > 0 && lr3 < sLRT[r3 - 1]) r3--;

    float* op = out + (size_t)i * SDIM + j0;
    if ((r0 == r1) & (r1 == r2) & (r2 == r3)) {
        const float2* row = shTab + r0 * HDIM;
#pragma unroll
        for (int h = 0; h < HDIM; h++) {
            const float2 sb = row[h];
            float4 v = make_float4(fmaf(sb.x, lr0, sb.y), fmaf(sb.x, lr1, sb.y),
                                   fmaf(sb.x, lr2, sb.y), fmaf(sb.x, lr3, sb.y));
            __stcs(reinterpret_cast<float4*>(op + (size_t)h * SDIM * SDIM), v);
        }
    } else {
#pragma unroll
        for (int h = 0; h < HDIM; h++) {
            const float2 a = shTab[r0 * HDIM + h];
            const float2 b = shTab[r1 * HDIM + h];
            const float2 cc = shTab[r2 * HDIM + h];
            const float2 d = shTab[r3 * HDIM + h];
            float4 v = make_float4(fmaf(a.x, lr0, a.y), fmaf(b.x, lr1, b.y),
                                   fmaf(cc.x, lr2, cc.y), fmaf(d.x, lr3, d.y));
            __stcs(reinterpret_cast<float4*>(op + (size_t)h * SDIM * SDIM), v);
        }
    }
}

extern "C" void kernel_launch(void* const* d_in, const int* in_sizes, int n_in,
                              void* d_out, int out_size) {
    // inputs: x(unused), w1[32], b1[32], w2[12*32], b2[12], c, L_multiplier, init_L
    const float* w1 = (const float*)d_in[1];
    const float* b1 = (const float*)d_in[2];
    const float* w2 = (const float*)d_in[3];
    const float* b2 = (const float*)d_in[4];
    const float* c  = (const float*)d_in[5];
    const float* Lm = (const float*)d_in[6];
    const float* iL = (const float*)d_in[7];
    (void)in_sizes; (void)n_in; (void)out_size;

    fire_pre<<<1, 32>>>(w1, b1, w2, b2, c, Lm, iL);

    cudaLaunchConfig_t cfg = {};
    cfg.gridDim  = dim3(SDIM);
    cfg.blockDim = dim3(512);
    cfg.dynamicSmemBytes = 0;
    cfg.stream = 0;
    cudaLaunchAttribute attrs[1];
    attrs[0].id = cudaLaunchAttributeProgrammaticStreamSerialization;
    attrs[0].val.programmaticStreamSerializationAllowed = 1;
    cfg.attrs = attrs;
    cfg.numAttrs = 1;
    cudaLaunchKernelEx(&cfg, fire_main, (float*)d_out);
}